// round 1
// baseline (speedup 1.0000x reference)
#include <cuda_runtime.h>
#include <math.h>

#define N_TOK 16384
#define D_DIM 1024
#define E_NUM 16
#define H_DIM 4096
#define NC_DIM 1000
#define CAP 2048
#define NB_GATE (N_TOK/8)

// ---------------- device scratch (static globals: no allocation allowed) ----
__device__ float g_disp[(size_t)E_NUM*CAP*D_DIM];   // 128 MB dispatched tokens
__device__ float g_h[(size_t)E_NUM*CAP*H_DIM];      // 512 MB hidden acts
__device__ float g_oute[(size_t)E_NUM*CAP*D_DIM];   // 128 MB expert outputs
__device__ float g_y[(size_t)N_TOK*D_DIM];          // 64 MB combined tokens
__device__ int   g_idx[N_TOK];
__device__ float g_gate[N_TOK];
__device__ int   g_lrank[N_TOK];
__device__ int   g_bhist[NB_GATE][E_NUM];
__device__ int   g_boff[NB_GATE][E_NUM];
__device__ int   g_count[E_NUM];
__device__ float g_probsum[E_NUM];
__device__ int   g_pos[N_TOK];

// ---------------- init: zero the probability accumulators ------------------
__global__ void k_init() {
    if (threadIdx.x < E_NUM) g_probsum[threadIdx.x] = 0.f;
}

// ---------------- gating: logits, softmax, argmax, block hist/ranks --------
// one warp per token, 8 tokens per block
__global__ void k_gate(const float* __restrict__ x, const float* __restrict__ Wg) {
    int warp = threadIdx.x >> 5, lane = threadIdx.x & 31;
    int t = blockIdx.x * 8 + warp;

    __shared__ float s_prob[E_NUM];
    __shared__ int   s_idx[8];
    if (threadIdx.x < E_NUM) s_prob[threadIdx.x] = 0.f;
    __syncthreads();

    float acc[E_NUM];
#pragma unroll
    for (int e = 0; e < E_NUM; e++) acc[e] = 0.f;

    const float* xr = x + (size_t)t * D_DIM;
    for (int j = 0; j < D_DIM / 32; j++) {
        float xv = xr[lane + 32 * j];
        const float* wr = Wg + (size_t)(lane + 32 * j) * E_NUM;
#pragma unroll
        for (int e = 0; e < E_NUM; e++) acc[e] = fmaf(xv, __ldg(wr + e), acc[e]);
    }
#pragma unroll
    for (int e = 0; e < E_NUM; e++) {
#pragma unroll
        for (int o = 16; o > 0; o >>= 1) acc[e] += __shfl_xor_sync(0xffffffffu, acc[e], o);
    }

    if (lane == 0) {
        float m = acc[0]; int ai = 0;
#pragma unroll
        for (int e = 1; e < E_NUM; e++) if (acc[e] > m) { m = acc[e]; ai = e; }
        float p[E_NUM]; float s = 0.f;
#pragma unroll
        for (int e = 0; e < E_NUM; e++) { p[e] = expf(acc[e] - m); s += p[e]; }
        float inv = 1.f / s;
#pragma unroll
        for (int e = 0; e < E_NUM; e++) atomicAdd(&s_prob[e], p[e] * inv);
        g_idx[t] = ai;
        g_gate[t] = p[ai] * inv;
        s_idx[warp] = ai;
    }
    __syncthreads();

    if (threadIdx.x == 0) {
        int cnt[E_NUM];
#pragma unroll
        for (int e = 0; e < E_NUM; e++) cnt[e] = 0;
#pragma unroll
        for (int w = 0; w < 8; w++) {
            int e = s_idx[w];
            g_lrank[blockIdx.x * 8 + w] = cnt[e];
            cnt[e]++;
        }
#pragma unroll
        for (int e = 0; e < E_NUM; e++) g_bhist[blockIdx.x][e] = cnt[e];
    }
    if (threadIdx.x < E_NUM) atomicAdd(&g_probsum[threadIdx.x], s_prob[threadIdx.x]);
}

// ---------------- exclusive scan of block histograms per expert ------------
// grid = E_NUM blocks, 256 threads each; each thread handles 8 gate-blocks
__global__ void k_scan() {
    const int PB = NB_GATE / 256;  // 8
    int e = blockIdx.x, tid = threadIdx.x;
    int v[PB]; int s = 0;
#pragma unroll
    for (int i = 0; i < PB; i++) { v[i] = g_bhist[tid * PB + i][e]; s += v[i]; }

    __shared__ int sh[256];
    sh[tid] = s;
    __syncthreads();
    for (int o = 1; o < 256; o <<= 1) {
        int q = (tid >= o) ? sh[tid - o] : 0;
        __syncthreads();
        sh[tid] += q;
        __syncthreads();
    }
    int excl = sh[tid] - s;
    int off = excl;
#pragma unroll
    for (int i = 0; i < PB; i++) { g_boff[tid * PB + i][e] = off; off += v[i]; }
    if (tid == 255) g_count[e] = sh[255];
}

// ---------------- dispatch: scatter kept tokens into [E, CAP, D] -----------
__global__ void k_dispatch(const float* __restrict__ x) {
    int t = blockIdx.x;
    int e = g_idx[t];
    int pos = g_boff[t >> 3][e] + g_lrank[t];
    if (pos < CAP) {
        if (threadIdx.x == 0) g_pos[t] = pos;
        const float4* src = (const float4*)(x + (size_t)t * D_DIM);
        float4* dst = (float4*)(g_disp + ((size_t)e * CAP + pos) * D_DIM);
        dst[threadIdx.x] = src[threadIdx.x];  // 256 threads x float4 = 1024 floats
    } else if (threadIdx.x == 0) {
        g_pos[t] = -1;
    }
}

// ---------------- SGEMM 128x128x8, 8x8 per thread, bias + optional gelu ----
__device__ __forceinline__ float gelu_tanh(float v) {
    float c = 0.7978845608028654f;
    float u = c * (v + 0.044715f * v * v * v);
    return 0.5f * v * (1.f + tanhf(u));
}

template <int ACT, bool NBOUND>
__global__ __launch_bounds__(256) void k_gemm(
    const float* __restrict__ A, const float* __restrict__ Bm,
    const float* __restrict__ bias, float* __restrict__ Cm,
    int Nn, int K,
    size_t strideAe, size_t strideBe, size_t strideBiasE, size_t strideCe,
    const int* __restrict__ cnt)
{
    int e = blockIdx.z;
    if (cnt) {
        int c = cnt[e]; if (c > CAP) c = CAP;
        if ((int)blockIdx.y * 128 >= c) return;  // skip tiles past expert count
    }
    A  += (size_t)e * strideAe;
    Bm += (size_t)e * strideBe;
    Cm += (size_t)e * strideCe;
    bias += (size_t)e * strideBiasE;

    __shared__ float As[8][128];
    __shared__ float Bs[8][128];

    int tid = threadIdx.x;
    int brow = blockIdx.y * 128, bcol = blockIdx.x * 128;
    int aRow = tid >> 1, aCol = (tid & 1) * 4;
    int bRow = tid >> 5, bCol = (tid & 31) * 4;
    int tx = tid & 15, ty = tid >> 4;

    float accv[8][8];
#pragma unroll
    for (int i = 0; i < 8; i++)
#pragma unroll
        for (int j = 0; j < 8; j++) accv[i][j] = 0.f;

    const float* Aptr = A + (size_t)(brow + aRow) * K + aCol;
    const float* Bptr = Bm + (size_t)bRow * Nn + bcol + bCol;

    for (int k0 = 0; k0 < K; k0 += 8) {
        float4 a4 = *(const float4*)Aptr;
        As[aCol + 0][aRow] = a4.x;
        As[aCol + 1][aRow] = a4.y;
        As[aCol + 2][aRow] = a4.z;
        As[aCol + 3][aRow] = a4.w;
        float4 b4;
        if (NBOUND) {
            int cbase = bcol + bCol;
            b4.x = (cbase + 0 < Nn) ? Bptr[0] : 0.f;
            b4.y = (cbase + 1 < Nn) ? Bptr[1] : 0.f;
            b4.z = (cbase + 2 < Nn) ? Bptr[2] : 0.f;
            b4.w = (cbase + 3 < Nn) ? Bptr[3] : 0.f;
        } else {
            b4 = *(const float4*)Bptr;
        }
        Bs[bRow][bCol + 0] = b4.x;
        Bs[bRow][bCol + 1] = b4.y;
        Bs[bRow][bCol + 2] = b4.z;
        Bs[bRow][bCol + 3] = b4.w;
        __syncthreads();

#pragma unroll
        for (int k = 0; k < 8; k++) {
            float ra[8], rb[8];
#pragma unroll
            for (int i = 0; i < 8; i++) ra[i] = As[k][ty * 8 + i];
#pragma unroll
            for (int j = 0; j < 8; j++) rb[j] = Bs[k][tx * 8 + j];
#pragma unroll
            for (int i = 0; i < 8; i++)
#pragma unroll
                for (int j = 0; j < 8; j++) accv[i][j] = fmaf(ra[i], rb[j], accv[i][j]);
        }
        __syncthreads();
        Aptr += 8;
        Bptr += (size_t)8 * Nn;
    }

#pragma unroll
    for (int i = 0; i < 8; i++) {
        int row = brow + ty * 8 + i;
#pragma unroll
        for (int j = 0; j < 8; j++) {
            int col = bcol + tx * 8 + j;
            if (!NBOUND || col < Nn) {
                float v = accv[i][j] + bias[col];
                if (ACT == 1) v = gelu_tanh(v);
                Cm[(size_t)row * Nn + col] = v;
            }
        }
    }
}

// ---------------- combine: gather expert outputs, scale by gate ------------
__global__ void k_combine() {
    int t = blockIdx.x;
    int pos = g_pos[t];
    float4* dst = (float4*)(g_y + (size_t)t * D_DIM);
    if (pos >= 0) {
        int e = g_idx[t];
        float g = g_gate[t];
        const float4* src = (const float4*)(g_oute + ((size_t)e * CAP + pos) * D_DIM);
        float4 v = src[threadIdx.x];
        v.x *= g; v.y *= g; v.z *= g; v.w *= g;
        dst[threadIdx.x] = v;
    } else {
        dst[threadIdx.x] = make_float4(0.f, 0.f, 0.f, 0.f);
    }
}

// ---------------- balancing loss --------------------------------------------
__global__ void k_loss(float* out, int out_size) {
    if (out_size <= N_TOK * NC_DIM) return;
    if (threadIdx.x == 0 && blockIdx.x == 0) {
        float s = 0.f;
        for (int e = 0; e < E_NUM; e++)
            s += ((float)g_count[e] / (float)N_TOK) * (g_probsum[e] / (float)N_TOK);
        out[(size_t)N_TOK * NC_DIM] = s * (float)E_NUM;
    }
}

// ---------------- launch -----------------------------------------------------
extern "C" void kernel_launch(void* const* d_in, const int* in_sizes, int n_in,
                              void* d_out, int out_size) {
    const float* x  = (const float*)d_in[0];
    const float* Wg = (const float*)d_in[1];
    const float* W1 = (const float*)d_in[2];
    const float* b1 = (const float*)d_in[3];
    const float* W2 = (const float*)d_in[4];
    const float* b2 = (const float*)d_in[5];
    const float* Wl = (const float*)d_in[6];
    const float* bl = (const float*)d_in[7];
    float* out = (float*)d_out;

    void *p_disp, *p_h, *p_oute, *p_y, *p_cnt;
    cudaGetSymbolAddress(&p_disp, g_disp);
    cudaGetSymbolAddress(&p_h, g_h);
    cudaGetSymbolAddress(&p_oute, g_oute);
    cudaGetSymbolAddress(&p_y, g_y);
    cudaGetSymbolAddress(&p_cnt, g_count);

    k_init<<<1, 32>>>();
    k_gate<<<NB_GATE, 256>>>(x, Wg);
    k_scan<<<E_NUM, 256>>>();
    k_dispatch<<<N_TOK, 256>>>(x);

    // FFN1: [CAP,1024] @ [1024,4096] + b1, gelu  (per expert, tile-skipped by count)
    {
        dim3 grid(H_DIM / 128, CAP / 128, E_NUM);
        k_gemm<1, false><<<grid, 256>>>(
            (const float*)p_disp, W1, b1, (float*)p_h,
            H_DIM, D_DIM,
            (size_t)CAP * D_DIM, (size_t)D_DIM * H_DIM, (size_t)H_DIM, (size_t)CAP * H_DIM,
            (const int*)p_cnt);
    }
    // FFN2: [CAP,4096] @ [4096,1024] + b2
    {
        dim3 grid(D_DIM / 128, CAP / 128, E_NUM);
        k_gemm<0, false><<<grid, 256>>>(
            (const float*)p_h, W2, b2, (float*)p_oute,
            D_DIM, H_DIM,
            (size_t)CAP * H_DIM, (size_t)H_DIM * D_DIM, (size_t)D_DIM, (size_t)CAP * D_DIM,
            (const int*)p_cnt);
    }

    k_combine<<<N_TOK, 256>>>();

    // classifier: [16384,1024] @ [1024,1000] + bl  -> out
    {
        dim3 grid((NC_DIM + 127) / 128, N_TOK / 128, 1);
        k_gemm<0, true><<<grid, 256>>>(
            (const float*)p_y, Wl, bl, out,
            NC_DIM, D_DIM,
            0, 0, 0, 0,
            nullptr);
    }

    k_loss<<<1, 32>>>(out, out_size);
}